// round 16
// baseline (speedup 1.0000x reference)
#include <cuda_runtime.h>

#define NBv   8
#define ND    512
#define NCHv  3
#define NMIXv 4
#define HD    128
#define NTILE 16
#define NARRIVE (NCHv * NTILE)   // 48 work blocks per batch

// ---------------- device scratch ----------------
__device__ float g_mid2[NBv * NCHv * NTILE * HD];  // per-(b,k,tile) w2_k . part/512
__device__ int   g_cnt[NBv];                        // zero-init
__device__ float g_sink[256];

__device__ __forceinline__ float ex2f(float x) {
    float r; asm("ex2.approx.f32 %0, %1;" : "=f"(r) : "f"(x)); return r;
}

// ---------------- shared-memory overlays ----------------
struct Tables {
    float4 A[ND];   // {u0m0, u0m1, u1m0, u1m1}
    float4 B[ND];   // {c0*y, c1*y, s0*y, s1*y}
    float4 C[ND];   // mixes 2,3 u's
    float4 D[ND];   // mixes 2,3 c*y / s*y
    float4 P[ND];   // {P0,P1,P2,P3}
};                                    // 40960 B
struct Reduce {
    float red[8][32][4];              // 4096 B
    float sred[2][HD];                // 1024 B
    float spart[HD];                  //  512 B  (layer-1 partial / 512)
};
struct TailSm {
    float h2[HD];
    float h3[HD];
    float sred[2][HD];
    float out5[NCHv * NMIXv][4];
};

// ---------------- the one kernel ----------------
// grid (17, 3, 8), 256 threads.
//   x < 16            : work block: pair + layer1 + w2_k matvec contribution
//   x == 16 && k == 0 : final block for b: sum mids + relu + layers 3..5
//   x == 16 && k != 0 : exits
__global__ void __launch_bounds__(256, 3) k_all(
    const float* __restrict__ xc, const float* __restrict__ yc,
    const float* __restrict__ mu, const float* __restrict__ istd,
    const float* __restrict__ w1p, const float* __restrict__ b1p,
    const float* __restrict__ w2, const float* __restrict__ b2,
    const float* __restrict__ w3, const float* __restrict__ b3,
    const float* __restrict__ w4, const float* __restrict__ b4,
    const float* __restrict__ w5, const float* __restrict__ b5,
    float* __restrict__ out)
{
    __shared__ union { Tables t; Reduce r; TailSm tl; } sm;   // 40960 B
    __shared__ float sy[ND];                                   //  2048 B

    const int tile = blockIdx.x, k = blockIdx.y, b = blockIdx.z;
    const int tid = threadIdx.x;

    if (tile == NTILE) {
        // =================== FINAL BLOCK: one per b ===================
        if (k != 0) return;

        // warm w3/w4/w5/biases into L1 (real loads) while work blocks run
        {
            float4 jk = make_float4(0.f, 0.f, 0.f, 0.f);
            const float4* p3 = (const float4*)w3;
            const float4* p4 = (const float4*)w4;
            for (int i = tid; i < 4096; i += 256) {
                const float4 v3 = p3[i], v4 = p4[i];
                jk.x += v3.x + v4.x; jk.y += v3.y + v4.y;
                jk.z += v3.z + v4.z; jk.w += v3.w + v4.w;
            }
            const float4* p5 = (const float4*)w5;
            for (int i = tid; i < 384; i += 256) {
                const float4 v = p5[i];
                jk.x += v.x; jk.y += v.y; jk.z += v.z; jk.w += v.w;
            }
            if (tid < HD) jk.x += b2[tid] + b3[tid] + b4[tid];
            if (tid < 12) jk.y += b5[tid];
            g_sink[tid] = jk.x + jk.y + jk.z + jk.w;
        }

        // spin until all 48 work blocks for this b arrived
        if (tid == 0) {
            while (*(volatile int*)&g_cnt[b] != NARRIVE) __nanosleep(64);
        }
        __syncthreads();
        __threadfence();   // acquire all g_mid2 stores

        const int j = tid & 127, q = tid >> 7;

        // h2 = relu(b2 + sum over 48 slots of g_mid2[b][slot][j]) — fixed order
        {
            const float* gm = &g_mid2[(b * NCHv) * NTILE * HD + j];
            float acc = 0.f;
            #pragma unroll
            for (int s = 0; s < 24; s++) acc += gm[(q * 24 + s) * HD];
            sm.tl.sred[q][j] = acc;
            __syncthreads();
            if (tid < HD)
                sm.tl.h2[tid] = fmaxf(sm.tl.sred[0][tid] + sm.tl.sred[1][tid]
                                      + b2[tid], 0.f);
            __syncthreads();
        }

        // layer 3: 128 -> 128 (q = 2-way split)
        {
            float acc0 = 0.f;
            const float4* wr = (const float4*)(w3 + j * HD + q * 64);
            const float4* xv = (const float4*)(sm.tl.h2 + q * 64);
            #pragma unroll
            for (int i = 0; i < 16; i++) {
                const float4 w = wr[i], x = xv[i];
                acc0 = fmaf(w.x, x.x, acc0); acc0 = fmaf(w.y, x.y, acc0);
                acc0 = fmaf(w.z, x.z, acc0); acc0 = fmaf(w.w, x.w, acc0);
            }
            sm.tl.sred[q][j] = acc0;
            __syncthreads();
            if (tid < HD)
                sm.tl.h3[tid] = fmaxf(sm.tl.sred[0][tid] + sm.tl.sred[1][tid]
                                      + b3[tid], 0.f);
            __syncthreads();
        }

        // layer 4: 128 -> 128 (into h2)
        {
            float acc0 = 0.f;
            const float4* wr = (const float4*)(w4 + j * HD + q * 64);
            const float4* xv = (const float4*)(sm.tl.h3 + q * 64);
            #pragma unroll
            for (int i = 0; i < 16; i++) {
                const float4 w = wr[i], x = xv[i];
                acc0 = fmaf(w.x, x.x, acc0); acc0 = fmaf(w.y, x.y, acc0);
                acc0 = fmaf(w.z, x.z, acc0); acc0 = fmaf(w.w, x.w, acc0);
            }
            sm.tl.sred[q][j] = acc0;
            __syncthreads();
            if (tid < HD)
                sm.tl.h2[tid] = fmaxf(sm.tl.sred[0][tid] + sm.tl.sred[1][tid]
                                      + b4[tid], 0.f);
            __syncthreads();
        }

        // layer 5: 128 -> 12
        if (tid < NCHv * NMIXv * 4) {
            const int j5 = tid >> 2, p = tid & 3;
            float acc = 0.f;
            const float4* wr = (const float4*)(w5 + j5 * HD + p * 32);
            const float4* xv = (const float4*)(sm.tl.h2 + p * 32);
            #pragma unroll
            for (int i = 0; i < 8; i++) {
                const float4 w = wr[i], x = xv[i];
                acc = fmaf(w.x, x.x, acc); acc = fmaf(w.y, x.y, acc);
                acc = fmaf(w.z, x.z, acc); acc = fmaf(w.w, x.w, acc);
            }
            sm.tl.out5[j5][p] = acc;
        }
        __syncthreads();
        if (tid < NCHv * NMIXv)
            out[b * (NCHv * NMIXv) + tid] =
                sm.tl.out5[tid][0] + sm.tl.out5[tid][1] + sm.tl.out5[tid][2]
                + sm.tl.out5[tid][3] + b5[tid];

        __syncthreads();
        if (tid == 0) g_cnt[b] = 0;   // reset for next graph replay
        return;
    }

    // =================== WORK BLOCK ===================
    const float PI2   = 6.2831853071795864f;
    const float ALPHA = 5.3364454f;   // 2pi*sqrt(0.5*log2(e))

    // ---- build full c-table (two points per thread), y folded into cos/sin ----
    #pragma unroll
    for (int c = tid; c < ND; c += 256) {
        const float x0 = xc[((b * ND + c) * 2 + 0) * NCHv + k];
        const float x1 = xc[((b * ND + c) * 2 + 1) * NCHv + k];
        const float y  = yc[(b * ND + c) * NCHv + k];
        float U0[4], U1[4], CO[4], SI[4], P[4];
        #pragma unroll
        for (int m = 0; m < NMIXv; m++) {
            const float u0 = x0 * istd[2 * m + 0] * ALPHA;
            const float u1 = x1 * istd[2 * m + 1] * ALPHA;
            float t = fmaf(x0, mu[2 * m + 0], x1 * mu[2 * m + 1]);
            t -= rintf(t);
            float sn, cn; __sincosf(PI2 * t, &sn, &cn);
            U0[m] = u0; U1[m] = u1; CO[m] = cn * y; SI[m] = sn * y;
            P[m] = -fmaf(u0, u0, u1 * u1);
        }
        sm.t.A[c] = make_float4(U0[0], U0[1], U1[0], U1[1]);
        sm.t.B[c] = make_float4(CO[0], CO[1], SI[0], SI[1]);
        sm.t.C[c] = make_float4(U0[2], U0[3], U1[2], U1[3]);
        sm.t.D[c] = make_float4(CO[2], CO[3], SI[2], SI[3]);
        sm.t.P[c] = make_float4(P[0], P[1], P[2], P[3]);
        sy[c] = y;
    }

    // ---- per-lane A-side values (scalar registers) ----
    const int al = tid & 31;
    const int cs = tid >> 5;          // c-split 0..7, uniform per warp
    const int a  = tile * 32 + al;

    float a00, a01, a02, a03;
    float a10, a11, a12, a13;
    float ca0, ca1, ca2, ca3;
    float sa0, sa1, sa2, sa3;
    float pa0, pa1, pa2, pa3;
    {
        const float x0 = xc[((b * ND + a) * 2 + 0) * NCHv + k];
        const float x1 = xc[((b * ND + a) * 2 + 1) * NCHv + k];
        float U0[4], U1[4], CO[4], SI[4], P[4];
        #pragma unroll
        for (int m = 0; m < NMIXv; m++) {
            const float u0 = x0 * istd[2 * m + 0] * ALPHA;
            const float u1 = x1 * istd[2 * m + 1] * ALPHA;
            float t = fmaf(x0, mu[2 * m + 0], x1 * mu[2 * m + 1]);
            t -= rintf(t);
            float sn, cn; __sincosf(PI2 * t, &sn, &cn);
            U0[m] = 2.0f * u0; U1[m] = 2.0f * u1; CO[m] = cn; SI[m] = sn;
            P[m] = -fmaf(u0, u0, u1 * u1);
        }
        a00 = U0[0]; a01 = U0[1]; a02 = U0[2]; a03 = U0[3];
        a10 = U1[0]; a11 = U1[1]; a12 = U1[2]; a13 = U1[3];
        ca0 = CO[0]; ca1 = CO[1]; ca2 = CO[2]; ca3 = CO[3];
        sa0 = SI[0]; sa1 = SI[1]; sa2 = SI[2]; sa3 = SI[3];
        pa0 = P[0];  pa1 = P[1];  pa2 = P[2];  pa3 = P[3];
    }
    __syncthreads();

    // ---- pair loop: warp = 32 a-lanes, 8 c-splits x 64 iters, scalar math ----
    float acc0 = 0.f, acc1 = 0.f, acc2 = 0.f, acc3 = 0.f;

    #pragma unroll 4
    for (int c = cs; c < ND; c += 8) {
        const float4 A = sm.t.A[c];
        const float4 B = sm.t.B[c];
        const float4 C = sm.t.C[c];
        const float4 D = sm.t.D[c];
        const float4 P = sm.t.P[c];
        {
            float s = pa0 + P.x;
            s = fmaf(A.x, a00, s);
            s = fmaf(A.z, a10, s);
            const float cv = fmaf(B.x, ca0, B.z * sa0);
            acc0 = fmaf(ex2f(s), cv, acc0);
        }
        {
            float s = pa1 + P.y;
            s = fmaf(A.y, a01, s);
            s = fmaf(A.w, a11, s);
            const float cv = fmaf(B.y, ca1, B.w * sa1);
            acc1 = fmaf(ex2f(s), cv, acc1);
        }
        {
            float s = pa2 + P.z;
            s = fmaf(C.x, a02, s);
            s = fmaf(C.z, a12, s);
            const float cv = fmaf(D.x, ca2, D.z * sa2);
            acc2 = fmaf(ex2f(s), cv, acc2);
        }
        {
            float s = pa3 + P.w;
            s = fmaf(C.y, a03, s);
            s = fmaf(C.w, a13, s);
            const float cv = fmaf(D.y, ca3, D.w * sa3);
            acc3 = fmaf(ex2f(s), cv, acc3);
        }
    }

    __syncthreads();   // tables dead; Reduce aliases them
    sm.r.red[cs][al][0] = acc0;
    sm.r.red[cs][al][1] = acc1;
    sm.r.red[cs][al][2] = acc2;
    sm.r.red[cs][al][3] = acc3;
    __syncthreads();

    // ---- reduce 8 c-splits, add zitter ----
    if (tid < 128) {
        const int lane = tid >> 2, m = tid & 3;
        float f = sm.r.red[0][lane][m];
        #pragma unroll
        for (int s = 1; s < 8; s++) f += sm.r.red[s][lane][m];
        f += 1.0e-4f * sy[tile * 32 + lane];
        sm.r.red[0][lane][m] = f;
    }
    __syncthreads();

    // ---- fused layer 1 on this tile's 32 a's (scaled by 1/512 = mean) ----
    {
        const int j = tid & 127, q = tid >> 7;
        const float wv0 = w1p[j * 5 + 0], wv1 = w1p[j * 5 + 1], wv2 = w1p[j * 5 + 2];
        const float wv3 = w1p[j * 5 + 3], wv4 = w1p[j * 5 + 4], bb = b1p[j];
        float acc = 0.f;
        #pragma unroll
        for (int aa = 0; aa < 16; aa++) {
            const int lane = q * 16 + aa;
            const float4 f = *(const float4*)&sm.r.red[0][lane][0];
            const float y = sy[tile * 32 + lane];
            float h = fmaf(wv0, f.x, bb);
            h = fmaf(wv1, f.y, h);
            h = fmaf(wv2, f.z, h);
            h = fmaf(wv3, f.w, h);
            h = fmaf(wv4, y, h);
            acc += fmaxf(h, 0.f);
        }
        sm.r.sred[q][j] = acc;
    }
    __syncthreads();
    if (tid < HD)
        sm.r.spart[tid] = (sm.r.sred[0][tid] + sm.r.sred[1][tid]) * (1.0f / 512.0f);
    __syncthreads();

    // ---- w2_k matvec: v[j2] = w2[j2, k*128 : +128] . spart ----
    {
        const int j2 = tid & 127, q = tid >> 7;
        float acc0 = 0.f, acc1 = 0.f;
        const float4* wr = (const float4*)(w2 + j2 * (NCHv * HD) + k * HD + q * 64);
        const float4* xv = (const float4*)(sm.r.spart + q * 64);
        #pragma unroll
        for (int i = 0; i < 16; i += 2) {
            { const float4 w = wr[i], x = xv[i];
              acc0 = fmaf(w.x, x.x, acc0); acc0 = fmaf(w.y, x.y, acc0);
              acc0 = fmaf(w.z, x.z, acc0); acc0 = fmaf(w.w, x.w, acc0); }
            { const float4 w = wr[i+1], x = xv[i+1];
              acc1 = fmaf(w.x, x.x, acc1); acc1 = fmaf(w.y, x.y, acc1);
              acc1 = fmaf(w.z, x.z, acc1); acc1 = fmaf(w.w, x.w, acc1); }
        }
        sm.r.sred[q][j2] = acc0 + acc1;
    }
    __syncthreads();
    if (tid < HD) {
        g_mid2[((b * NCHv + k) * NTILE + tile) * HD + tid] =
            sm.r.sred[0][tid] + sm.r.sred[1][tid];
    }

    // ---- release: publish g_mid2, then signal arrival ----
    __threadfence();
    __syncthreads();
    if (tid == 0) atomicAdd(&g_cnt[b], 1);
}

// ---------------- launch ----------------
extern "C" void kernel_launch(void* const* d_in, const int* in_sizes, int n_in,
                              void* d_out, int out_size)
{
    const float* xc   = (const float*)d_in[0];
    const float* yc   = (const float*)d_in[1];
    const float* mu   = (const float*)d_in[2];
    const float* istd = (const float*)d_in[3];
    const float* w1   = (const float*)d_in[4];
    const float* b1   = (const float*)d_in[5];
    const float* w2   = (const float*)d_in[6];
    const float* b2   = (const float*)d_in[7];
    const float* w3   = (const float*)d_in[8];
    const float* b3   = (const float*)d_in[9];
    const float* w4   = (const float*)d_in[10];
    const float* b4   = (const float*)d_in[11];
    const float* w5   = (const float*)d_in[12];
    const float* b5   = (const float*)d_in[13];
    float* out = (float*)d_out;

    dim3 g1(NTILE + 1, NCHv, NBv);   // 17 x 3 x 8 = 408 blocks, 256 threads
    k_all<<<g1, 256>>>(xc, yc, mu, istd, w1, b1,
                       w2, b2, w3, b3, w4, b4, w5, b5, out);
}

// round 17
// speedup vs baseline: 1.1552x; 1.1552x over previous
#include <cuda_runtime.h>

#define NBv   8
#define ND    512
#define NCHv  3
#define NMIXv 4
#define HD    128
#define NTILE 16

// ---------------- device scratch ----------------
__device__ float g_part[NBv * NCHv * NTILE * HD];  // per-(b,k,tile) layer1 partials
__device__ float g_mid[NBv * NCHv * HD];            // per-(b,k) w2_k . h1_k
__device__ int   g_cntk[NBv * NCHv];                // per-(b,k) tile arrivals (zero-init)
__device__ int   g_cnt2[NBv];                       // per-b mid arrivals (zero-init)
__device__ float g_sink[256];

__device__ __forceinline__ float ex2f(float x) {
    float r; asm("ex2.approx.f32 %0, %1;" : "=f"(r) : "f"(x)); return r;
}

// ---------------- shared-memory overlays ----------------
struct Tables {
    float4 A[ND];   // {u0m0, u0m1, u1m0, u1m1}
    float4 B[ND];   // {c0*y, c1*y, s0*y, s1*y}
    float4 C[ND];   // mixes 2,3 u's
    float4 D[ND];   // mixes 2,3 c*y / s*y
    float4 P[ND];   // {P0,P1,P2,P3}
};                                    // 40960 B
struct Reduce {
    float red[8][32][4];              // 4096 B
    float sred[2][HD];                // 1024 B
};
struct MidSm {
    float h1k[HD];
    float sred[2][HD];
};
struct TailSm {
    float h2[HD];
    float h3[HD];
    float sred[2][HD];
    float out5[NCHv * NMIXv][4];
};

// ---------------- the one kernel ----------------
// grid (18, 3, 8), 256 threads.
//   x < 16             : pair + layer1 work block
//   x == 16            : mid block for (b,k): h1_k reduce + w2_k matvec
//   x == 17 && k == 0  : final block for b: relu + layers 3..5
//   x == 17 && k != 0  : exits
__global__ void __launch_bounds__(256, 3) k_all(
    const float* __restrict__ xc, const float* __restrict__ yc,
    const float* __restrict__ mu, const float* __restrict__ istd,
    const float* __restrict__ w1p, const float* __restrict__ b1p,
    const float* __restrict__ w2, const float* __restrict__ b2,
    const float* __restrict__ w3, const float* __restrict__ b3,
    const float* __restrict__ w4, const float* __restrict__ b4,
    const float* __restrict__ w5, const float* __restrict__ b5,
    float* __restrict__ out)
{
    __shared__ union { Tables t; Reduce r; MidSm md; TailSm tl; } sm;   // 40960 B
    __shared__ float sy[ND];                                             //  2048 B

    const int tile = blockIdx.x, k = blockIdx.y, b = blockIdx.z;
    const int tid = threadIdx.x;

    if (tile == NTILE) {
        // =================== MID BLOCK: one per (b,k) ===================
        {
            float4 jk = make_float4(0.f, 0.f, 0.f, 0.f);
            const float4* p2 = (const float4*)w2;
            for (int i = tid; i < 4096; i += 256) {
                const int r = i >> 5, c = i & 31;
                const float4 v = p2[r * 96 + k * 32 + c];
                jk.x += v.x; jk.y += v.y; jk.z += v.z; jk.w += v.w;
            }
            if (k == 0) g_sink[tid] = jk.x + jk.y + jk.z + jk.w;
            else if (jk.x == 1e33f) g_sink[tid] = jk.y;   // never true; keeps loads
        }

        if (tid == 0) {
            while (*(volatile int*)&g_cntk[b * NCHv + k] != NTILE) __nanosleep(64);
        }
        __syncthreads();
        __threadfence();   // acquire g_part stores

        if (tid < HD) {
            const float* p = &g_part[((b * NCHv + k) * NTILE) * HD + tid];
            float acc = 0.f;
            #pragma unroll
            for (int t = 0; t < NTILE; t++) acc += p[t * HD];
            sm.md.h1k[tid] = acc * (1.0f / 512.0f);
        }
        __syncthreads();

        {
            const int j2 = tid & 127, q = tid >> 7;
            float acc0 = 0.f, acc1 = 0.f;
            const float4* wr = (const float4*)(w2 + j2 * (NCHv * HD) + k * HD + q * 64);
            const float4* xv = (const float4*)(sm.md.h1k + q * 64);
            #pragma unroll
            for (int i = 0; i < 16; i += 2) {
                { const float4 w = wr[i], x = xv[i];
                  acc0 = fmaf(w.x, x.x, acc0); acc0 = fmaf(w.y, x.y, acc0);
                  acc0 = fmaf(w.z, x.z, acc0); acc0 = fmaf(w.w, x.w, acc0); }
                { const float4 w = wr[i+1], x = xv[i+1];
                  acc1 = fmaf(w.x, x.x, acc1); acc1 = fmaf(w.y, x.y, acc1);
                  acc1 = fmaf(w.z, x.z, acc1); acc1 = fmaf(w.w, x.w, acc1); }
            }
            sm.md.sred[q][j2] = acc0 + acc1;
        }
        __syncthreads();
        if (tid < HD)
            g_mid[(b * NCHv + k) * HD + tid] = sm.md.sred[0][tid] + sm.md.sred[1][tid];

        __threadfence();
        __syncthreads();
        if (tid == 0) {
            g_cntk[b * NCHv + k] = 0;
            atomicAdd(&g_cnt2[b], 1);
        }
        return;
    }

    if (tile == NTILE + 1) {
        // =================== FINAL BLOCK: one per b ===================
        if (k != 0) return;

        {
            float4 jk = make_float4(0.f, 0.f, 0.f, 0.f);
            const float4* p3 = (const float4*)w3;
            const float4* p4 = (const float4*)w4;
            for (int i = tid; i < 4096; i += 256) {
                const float4 v3 = p3[i], v4 = p4[i];
                jk.x += v3.x + v4.x; jk.y += v3.y + v4.y;
                jk.z += v3.z + v4.z; jk.w += v3.w + v4.w;
            }
            const float4* p5 = (const float4*)w5;
            for (int i = tid; i < 384; i += 256) {
                const float4 v = p5[i];
                jk.x += v.x; jk.y += v.y; jk.z += v.z; jk.w += v.w;
            }
            if (tid < HD) jk.x += b2[tid] + b3[tid] + b4[tid];
            if (tid < 12) jk.y += b5[tid];
            g_sink[tid] = jk.x + jk.y + jk.z + jk.w;
        }

        if (tid == 0) {
            while (*(volatile int*)&g_cnt2[b] != NCHv) __nanosleep(64);
        }
        __syncthreads();
        __threadfence();   // acquire g_mid stores

        const int j = tid & 127, q = tid >> 7;

        if (tid < HD) {
            const float* gm = &g_mid[b * NCHv * HD];
            sm.tl.h2[tid] = fmaxf(gm[tid] + gm[HD + tid] + gm[2 * HD + tid]
                                  + b2[tid], 0.f);
        }
        __syncthreads();

        // layer 3
        {
            float acc0 = 0.f;
            const float4* wr = (const float4*)(w3 + j * HD + q * 64);
            const float4* xv = (const float4*)(sm.tl.h2 + q * 64);
            #pragma unroll
            for (int i = 0; i < 16; i++) {
                const float4 w = wr[i], x = xv[i];
                acc0 = fmaf(w.x, x.x, acc0); acc0 = fmaf(w.y, x.y, acc0);
                acc0 = fmaf(w.z, x.z, acc0); acc0 = fmaf(w.w, x.w, acc0);
            }
            sm.tl.sred[q][j] = acc0;
            __syncthreads();
            if (tid < HD)
                sm.tl.h3[tid] = fmaxf(sm.tl.sred[0][tid] + sm.tl.sred[1][tid]
                                      + b3[tid], 0.f);
            __syncthreads();
        }

        // layer 4
        {
            float acc0 = 0.f;
            const float4* wr = (const float4*)(w4 + j * HD + q * 64);
            const float4* xv = (const float4*)(sm.tl.h3 + q * 64);
            #pragma unroll
            for (int i = 0; i < 16; i++) {
                const float4 w = wr[i], x = xv[i];
                acc0 = fmaf(w.x, x.x, acc0); acc0 = fmaf(w.y, x.y, acc0);
                acc0 = fmaf(w.z, x.z, acc0); acc0 = fmaf(w.w, x.w, acc0);
            }
            sm.tl.sred[q][j] = acc0;
            __syncthreads();
            if (tid < HD)
                sm.tl.h2[tid] = fmaxf(sm.tl.sred[0][tid] + sm.tl.sred[1][tid]
                                      + b4[tid], 0.f);
            __syncthreads();
        }

        // layer 5
        if (tid < NCHv * NMIXv * 4) {
            const int j5 = tid >> 2, p = tid & 3;
            float acc = 0.f;
            const float4* wr = (const float4*)(w5 + j5 * HD + p * 32);
            const float4* xv = (const float4*)(sm.tl.h2 + p * 32);
            #pragma unroll
            for (int i = 0; i < 8; i++) {
                const float4 w = wr[i], x = xv[i];
                acc = fmaf(w.x, x.x, acc); acc = fmaf(w.y, x.y, acc);
                acc = fmaf(w.z, x.z, acc); acc = fmaf(w.w, x.w, acc);
            }
            sm.tl.out5[j5][p] = acc;
        }
        __syncthreads();
        if (tid < NCHv * NMIXv)
            out[b * (NCHv * NMIXv) + tid] =
                sm.tl.out5[tid][0] + sm.tl.out5[tid][1] + sm.tl.out5[tid][2]
                + sm.tl.out5[tid][3] + b5[tid];

        __syncthreads();
        if (tid == 0) g_cnt2[b] = 0;
        return;
    }

    // =================== WORK BLOCK ===================
    const float PI2   = 6.2831853071795864f;
    const float ALPHA = 5.3364454f;   // 2pi*sqrt(0.5*log2(e))

    // ---- build full c-table (two points per thread), y folded into cos/sin ----
    #pragma unroll
    for (int c = tid; c < ND; c += 256) {
        const float x0 = xc[((b * ND + c) * 2 + 0) * NCHv + k];
        const float x1 = xc[((b * ND + c) * 2 + 1) * NCHv + k];
        const float y  = yc[(b * ND + c) * NCHv + k];
        float U0[4], U1[4], CO[4], SI[4], P[4];
        #pragma unroll
        for (int m = 0; m < NMIXv; m++) {
            const float u0 = x0 * istd[2 * m + 0] * ALPHA;
            const float u1 = x1 * istd[2 * m + 1] * ALPHA;
            float t = fmaf(x0, mu[2 * m + 0], x1 * mu[2 * m + 1]);
            t -= rintf(t);
            float sn, cn; __sincosf(PI2 * t, &sn, &cn);
            U0[m] = u0; U1[m] = u1; CO[m] = cn * y; SI[m] = sn * y;
            P[m] = -fmaf(u0, u0, u1 * u1);
        }
        sm.t.A[c] = make_float4(U0[0], U0[1], U1[0], U1[1]);
        sm.t.B[c] = make_float4(CO[0], CO[1], SI[0], SI[1]);
        sm.t.C[c] = make_float4(U0[2], U0[3], U1[2], U1[3]);
        sm.t.D[c] = make_float4(CO[2], CO[3], SI[2], SI[3]);
        sm.t.P[c] = make_float4(P[0], P[1], P[2], P[3]);
        sy[c] = y;
    }

    // ---- per-lane A-side values (scalar registers) ----
    const int al = tid & 31;
    const int cs = tid >> 5;          // c-split 0..7, uniform per warp
    const int a  = tile * 32 + al;

    float a00, a01, a02, a03;
    float a10, a11, a12, a13;
    float ca0, ca1, ca2, ca3;
    float sa0, sa1, sa2, sa3;
    float pa0, pa1, pa2, pa3;
    {
        const float x0 = xc[((b * ND + a) * 2 + 0) * NCHv + k];
        const float x1 = xc[((b * ND + a) * 2 + 1) * NCHv + k];
        float U0[4], U1[4], CO[4], SI[4], P[4];
        #pragma unroll
        for (int m = 0; m < NMIXv; m++) {
            const float u0 = x0 * istd[2 * m + 0] * ALPHA;
            const float u1 = x1 * istd[2 * m + 1] * ALPHA;
            float t = fmaf(x0, mu[2 * m + 0], x1 * mu[2 * m + 1]);
            t -= rintf(t);
            float sn, cn; __sincosf(PI2 * t, &sn, &cn);
            U0[m] = 2.0f * u0; U1[m] = 2.0f * u1; CO[m] = cn; SI[m] = sn;
            P[m] = -fmaf(u0, u0, u1 * u1);
        }
        a00 = U0[0]; a01 = U0[1]; a02 = U0[2]; a03 = U0[3];
        a10 = U1[0]; a11 = U1[1]; a12 = U1[2]; a13 = U1[3];
        ca0 = CO[0]; ca1 = CO[1]; ca2 = CO[2]; ca3 = CO[3];
        sa0 = SI[0]; sa1 = SI[1]; sa2 = SI[2]; sa3 = SI[3];
        pa0 = P[0];  pa1 = P[1];  pa2 = P[2];  pa3 = P[3];
    }
    __syncthreads();

    // ---- pair loop: re/im accumulators (cos rotation applied AFTER loop) ----
    // feature_m = ca_m * sum_c e*cy + sa_m * sum_c e*sy   (linear in c-sum)
    float re0 = 0.f, re1 = 0.f, re2 = 0.f, re3 = 0.f;
    float im0 = 0.f, im1 = 0.f, im2 = 0.f, im3 = 0.f;

    #pragma unroll 4
    for (int c = cs; c < ND; c += 8) {
        const float4 A = sm.t.A[c];
        const float4 B = sm.t.B[c];
        const float4 C = sm.t.C[c];
        const float4 D = sm.t.D[c];
        const float4 P = sm.t.P[c];
        {
            float s = pa0 + P.x;
            s = fmaf(A.x, a00, s);
            s = fmaf(A.z, a10, s);
            const float e = ex2f(s);
            re0 = fmaf(e, B.x, re0);
            im0 = fmaf(e, B.z, im0);
        }
        {
            float s = pa1 + P.y;
            s = fmaf(A.y, a01, s);
            s = fmaf(A.w, a11, s);
            const float e = ex2f(s);
            re1 = fmaf(e, B.y, re1);
            im1 = fmaf(e, B.w, im1);
        }
        {
            float s = pa2 + P.z;
            s = fmaf(C.x, a02, s);
            s = fmaf(C.z, a12, s);
            const float e = ex2f(s);
            re2 = fmaf(e, D.x, re2);
            im2 = fmaf(e, D.z, im2);
        }
        {
            float s = pa3 + P.w;
            s = fmaf(C.y, a03, s);
            s = fmaf(C.w, a13, s);
            const float e = ex2f(s);
            re3 = fmaf(e, D.y, re3);
            im3 = fmaf(e, D.w, im3);
        }
    }

    // apply per-lane rotation to this warp's partial sums (linear, so valid per split)
    const float f0 = fmaf(ca0, re0, sa0 * im0);
    const float f1 = fmaf(ca1, re1, sa1 * im1);
    const float f2 = fmaf(ca2, re2, sa2 * im2);
    const float f3 = fmaf(ca3, re3, sa3 * im3);

    __syncthreads();   // tables dead; Reduce aliases them
    sm.r.red[cs][al][0] = f0;
    sm.r.red[cs][al][1] = f1;
    sm.r.red[cs][al][2] = f2;
    sm.r.red[cs][al][3] = f3;
    __syncthreads();

    // ---- reduce 8 c-splits, add zitter ----
    if (tid < 128) {
        const int lane = tid >> 2, m = tid & 3;
        float f = sm.r.red[0][lane][m];
        #pragma unroll
        for (int s = 1; s < 8; s++) f += sm.r.red[s][lane][m];
        f += 1.0e-4f * sy[tile * 32 + lane];
        sm.r.red[0][lane][m] = f;
    }
    __syncthreads();

    // ---- fused layer 1 on this tile's 32 a's ----
    {
        const int j = tid & 127, q = tid >> 7;
        const float wv0 = w1p[j * 5 + 0], wv1 = w1p[j * 5 + 1], wv2 = w1p[j * 5 + 2];
        const float wv3 = w1p[j * 5 + 3], wv4 = w1p[j * 5 + 4], bb = b1p[j];
        float acc = 0.f;
        #pragma unroll
        for (int aa = 0; aa < 16; aa++) {
            const int lane = q * 16 + aa;
            const float4 f = *(const float4*)&sm.r.red[0][lane][0];
            const float y = sy[tile * 32 + lane];
            float h = fmaf(wv0, f.x, bb);
            h = fmaf(wv1, f.y, h);
            h = fmaf(wv2, f.z, h);
            h = fmaf(wv3, f.w, h);
            h = fmaf(wv4, y, h);
            acc += fmaxf(h, 0.f);
        }
        sm.r.sred[q][j] = acc;
    }
    __syncthreads();
    if (tid < HD) {
        g_part[((b * NCHv + k) * NTILE + tile) * HD + tid] =
            sm.r.sred[0][tid] + sm.r.sred[1][tid];
    }

    // ---- release: publish g_part, then signal this channel's arrival ----
    __threadfence();
    __syncthreads();
    if (tid == 0) atomicAdd(&g_cntk[b * NCHv + k], 1);
}

// ---------------- launch ----------------
extern "C" void kernel_launch(void* const* d_in, const int* in_sizes, int n_in,
                              void* d_out, int out_size)
{
    const float* xc   = (const float*)d_in[0];
    const float* yc   = (const float*)d_in[1];
    const float* mu   = (const float*)d_in[2];
    const float* istd = (const float*)d_in[3];
    const float* w1   = (const float*)d_in[4];
    const float* b1   = (const float*)d_in[5];
    const float* w2   = (const float*)d_in[6];
    const float* b2   = (const float*)d_in[7];
    const float* w3   = (const float*)d_in[8];
    const float* b3   = (const float*)d_in[9];
    const float* w4   = (const float*)d_in[10];
    const float* b4   = (const float*)d_in[11];
    const float* w5   = (const float*)d_in[12];
    const float* b5   = (const float*)d_in[13];
    float* out = (float*)d_out;

    dim3 g1(NTILE + 2, NCHv, NBv);   // 18 x 3 x 8 = 432 blocks, 256 threads
    k_all<<<g1, 256>>>(xc, yc, mu, istd, w1, b1,
                       w2, b2, w3, b3, w4, b4, w5, b5, out);
}